// round 1
// baseline (speedup 1.0000x reference)
#include <cuda_runtime.h>
#include <cstdint>

// Problem constants (fixed shapes for this problem)
#define N_PTS  65536
#define DIM    128
#define D4     (DIM / 4)        // 32 float4 per point
#define NSTG   4
#define KCB    2048
#define KCHUNK 32
#define NCHUNK (KCB / KCHUNK)   // 64
#define TPB    128
#define NBLK   (N_PTS / TPB)    // 512

// Scratch (no cudaMalloc allowed)
__device__ float g_cnorm[NSTG * KCB];
__device__ float g_partial[NBLK];

__device__ __forceinline__ void cp_async16(void* smem_ptr, const void* gmem_ptr) {
    unsigned s = (unsigned)__cvta_generic_to_shared(smem_ptr);
    asm volatile("cp.async.cg.shared.global [%0], [%1], 16;" :: "r"(s), "l"(gmem_ptr));
}
__device__ __forceinline__ void cp_commit() { asm volatile("cp.async.commit_group;"); }
__device__ __forceinline__ void cp_wait1()  { asm volatile("cp.async.wait_group 1;"); }
__device__ __forceinline__ void cp_wait0()  { asm volatile("cp.async.wait_group 0;"); }

// ---------------------------------------------------------------------------
// Kernel 0: per-codeword squared norms, g_cnorm[s*K + k] = sum_d C[s,k,d]^2
// ---------------------------------------------------------------------------
__global__ void rvq_cnorm_kernel(const float* __restrict__ cb) {
    int c = blockIdx.x * blockDim.x + threadIdx.x;
    if (c >= NSTG * KCB) return;
    const float4* row = (const float4*)(cb + (size_t)c * DIM);
    float s = 0.f;
#pragma unroll
    for (int i = 0; i < D4; i++) {
        float4 v = row[i];
        s += v.x * v.x + v.y * v.y + v.z * v.z + v.w * v.w;
    }
    g_cnorm[c] = s;
}

// ---------------------------------------------------------------------------
// Kernel 1: main RVQ. One point per thread; residual in registers; codewords
// streamed through double-buffered smem chunks (broadcast reads).
// ---------------------------------------------------------------------------
__global__ void __launch_bounds__(TPB, 3)
rvq_main_kernel(const float* __restrict__ x,
                const float* __restrict__ cb,
                float* __restrict__ out) {
    __shared__ float4 sm[2][KCHUNK * D4];   // 2 x 16KB
    __shared__ float  red[TPB];

    const int tid = threadIdx.x;
    const int n   = blockIdx.x * TPB + tid;

    const float4* x4 = (const float4*)x;

    // residual starts as x[n]
    float4 r[D4];
#pragma unroll
    for (int d = 0; d < D4; d++) r[d] = x4[(size_t)n * D4 + d];

    float loss_local = 0.f;

    for (int s = 0; s < NSTG; s++) {
        const float4* C4 = (const float4*)(cb + (size_t)s * KCB * DIM);
        const float*  cn = g_cnorm + s * KCB;

        // ||r||^2 for this stage
        float rn = 0.f;
#pragma unroll
        for (int d = 0; d < D4; d++)
            rn += r[d].x * r[d].x + r[d].y * r[d].y + r[d].z * r[d].z + r[d].w * r[d].w;

        float best  = 3.402823466e38f;
        int   bestk = 0;

        // prologue: async-load chunk 0 into buffer 0
        {
            const float4* src = C4;
            float4* dst = sm[0];
#pragma unroll
            for (int j = 0; j < 8; j++)
                cp_async16(&dst[tid + TPB * j], &src[tid + TPB * j]);
            cp_commit();
        }

        for (int ch = 0; ch < NCHUNK; ch++) {
            const int buf = ch & 1;
            if (ch + 1 < NCHUNK) {
                const float4* src = C4 + (size_t)(ch + 1) * KCHUNK * D4;
                float4* dst = sm[buf ^ 1];
#pragma unroll
                for (int j = 0; j < 8; j++)
                    cp_async16(&dst[tid + TPB * j], &src[tid + TPB * j]);
                cp_commit();
                cp_wait1();     // chunk ch is complete (ch+1 may be in flight)
            } else {
                cp_wait0();
            }
            __syncthreads();

            const int kbase = ch * KCHUNK;
            const float4* smb = sm[buf];
#pragma unroll 1
            for (int kk = 0; kk < KCHUNK; kk += 2) {
                const float4* c0 = smb + (kk)     * D4;
                const float4* c1 = smb + (kk + 1) * D4;
                float4 a0 = make_float4(0.f, 0.f, 0.f, 0.f);
                float4 a1 = make_float4(0.f, 0.f, 0.f, 0.f);
#pragma unroll
                for (int d = 0; d < D4; d++) {
                    float4 ca = c0[d];
                    float4 cbv = c1[d];
                    a0.x = fmaf(r[d].x, ca.x,  a0.x);
                    a0.y = fmaf(r[d].y, ca.y,  a0.y);
                    a0.z = fmaf(r[d].z, ca.z,  a0.z);
                    a0.w = fmaf(r[d].w, ca.w,  a0.w);
                    a1.x = fmaf(r[d].x, cbv.x, a1.x);
                    a1.y = fmaf(r[d].y, cbv.y, a1.y);
                    a1.z = fmaf(r[d].z, cbv.z, a1.z);
                    a1.w = fmaf(r[d].w, cbv.w, a1.w);
                }
                float dot0 = (a0.x + a0.y) + (a0.z + a0.w);
                float dot1 = (a1.x + a1.y) + (a1.z + a1.w);
                int k0 = kbase + kk;
                int k1 = k0 + 1;
                float s0 = fmaf(-2.f, dot0, __ldg(&cn[k0]));
                float s1 = fmaf(-2.f, dot1, __ldg(&cn[k1]));
                // ascending k + strict < == first-occurrence argmin
                if (s0 < best) { best = s0; bestk = k0; }
                if (s1 < best) { best = s1; bestk = k1; }
            }
            __syncthreads();
        }

        // loss contribution: min squared distance = ||r||^2 + (cnorm - 2 r.c)
        loss_local += rn + best;

        // residual update: r -= C[bestk]   (bitwise-identical to reference order)
        const float4* cw = C4 + (size_t)bestk * D4;
#pragma unroll
        for (int d = 0; d < D4; d++) {
            float4 c = __ldg(&cw[d]);
            r[d].x -= c.x; r[d].y -= c.y; r[d].z -= c.z; r[d].w -= c.w;
        }

        // indices output: [N, S] as float, after x_q block and loss scalar
        out[(size_t)N_PTS * DIM + 1 + (size_t)n * NSTG + s] = (float)bestk;
    }

    // x_q = x - residual_final
    float4* out4 = (float4*)out;
#pragma unroll
    for (int d = 0; d < D4; d++) {
        float4 xv = x4[(size_t)n * D4 + d];
        float4 o;
        o.x = xv.x - r[d].x;
        o.y = xv.y - r[d].y;
        o.z = xv.z - r[d].z;
        o.w = xv.w - r[d].w;
        out4[(size_t)n * D4 + d] = o;
    }

    // deterministic block reduction of loss partials
    red[tid] = loss_local;
    __syncthreads();
#pragma unroll
    for (int off = TPB / 2; off > 0; off >>= 1) {
        if (tid < off) red[tid] += red[tid + off];
        __syncthreads();
    }
    if (tid == 0) g_partial[blockIdx.x] = red[0];
}

// ---------------------------------------------------------------------------
// Kernel 2: final deterministic reduction -> mean_loss scalar
// mean_loss = (1 + BETA) * sum(dist_min) / (S * N * D),  BETA = 0.25
// ---------------------------------------------------------------------------
__global__ void rvq_loss_kernel(float* __restrict__ out) {
    __shared__ float red[NBLK];
    int t = threadIdx.x;
    red[t] = g_partial[t];
    __syncthreads();
#pragma unroll
    for (int off = NBLK / 2; off > 0; off >>= 1) {
        if (t < off) red[t] += red[t + off];
        __syncthreads();
    }
    if (t == 0) {
        float scale = 1.25f / ((float)NSTG * (float)N_PTS * (float)DIM);
        out[(size_t)N_PTS * DIM] = red[0] * scale;
    }
}

// ---------------------------------------------------------------------------
extern "C" void kernel_launch(void* const* d_in, const int* in_sizes, int n_in,
                              void* d_out, int out_size) {
    const float* x  = (const float*)d_in[0];   // [N, D] float32
    const float* cb = (const float*)d_in[1];   // [S, K, D] float32
    float* out = (float*)d_out;                // [N*D | 1 | N*S] float32

    rvq_cnorm_kernel<<<(NSTG * KCB + 127) / 128, 128>>>(cb);
    rvq_main_kernel<<<NBLK, TPB>>>(x, cb, out);
    rvq_loss_kernel<<<1, NBLK>>>(out);
}

// round 2
// speedup vs baseline: 2.7524x; 2.7524x over previous
#include <cuda_runtime.h>
#include <cstdint>

// Fixed problem shapes
#define N_PTS  65536
#define DIM    128
#define NSTG   4
#define KCB    2048
#define KCHUNK 32
#define NCHUNK (KCB / KCHUNK)   // 64
#define TPB    128
#define NBLK   (N_PTS / TPB)    // 512

typedef unsigned long long u64;

// Scratch (no cudaMalloc allowed)
__device__ float g_chalf[NSTG * KCB];    // 0.5 * ||C_k||^2
__device__ float g_partial[NBLK];

// ---------------- packed f32x2 helpers (Blackwell dual-fp32 datapath) -------
__device__ __forceinline__ u64 fma2(u64 a, u64 b, u64 c) {
    u64 d;
    asm("fma.rn.f32x2 %0, %1, %2, %3;" : "=l"(d) : "l"(a), "l"(b), "l"(c));
    return d;
}
__device__ __forceinline__ void unpack2(u64 v, float& lo, float& hi) {
    asm("mov.b64 {%0, %1}, %2;" : "=f"(lo), "=f"(hi) : "l"(v));
}
__device__ __forceinline__ u64 pack2(float lo, float hi) {
    u64 v;
    asm("mov.b64 %0, {%1, %2};" : "=l"(v) : "f"(lo), "f"(hi));
    return v;
}

__device__ __forceinline__ void cp_async16(void* smem_ptr, const void* gmem_ptr) {
    unsigned s = (unsigned)__cvta_generic_to_shared(smem_ptr);
    asm volatile("cp.async.cg.shared.global [%0], [%1], 16;" :: "r"(s), "l"(gmem_ptr));
}
__device__ __forceinline__ void cp_commit() { asm volatile("cp.async.commit_group;"); }
__device__ __forceinline__ void cp_wait1()  { asm volatile("cp.async.wait_group 1;"); }
__device__ __forceinline__ void cp_wait0()  { asm volatile("cp.async.wait_group 0;"); }

// swizzle of the float4-index inside one codeword (32 float4):
// slice j = i>>3 stays, low 3 bits rotated by j -> the 4 lane-slices of a
// group hit 4 distinct bank quads at every inner step.
__device__ __forceinline__ int swz(int i) {
    int j = i >> 3;
    return (i & ~7) | ((i + j) & 7);
}

// ---------------------------------------------------------------------------
// Kernel 0: half squared norms  g_chalf[s*K+k] = 0.5 * sum_d C[s,k,d]^2
// ---------------------------------------------------------------------------
__global__ void rvq_cnorm_kernel(const float* __restrict__ cb) {
    int c = blockIdx.x * blockDim.x + threadIdx.x;
    if (c >= NSTG * KCB) return;
    const float4* row = (const float4*)(cb + (size_t)c * DIM);
    float s = 0.f;
#pragma unroll
    for (int i = 0; i < 32; i++) {
        float4 v = row[i];
        s += v.x * v.x + v.y * v.y + v.z * v.z + v.w * v.w;
    }
    g_chalf[c] = 0.5f * s;
}

// ---------------------------------------------------------------------------
// Kernel 1: main RVQ.
// Warp layout: group = 4 lanes, 4 points per thread (16 pts... no: 8 groups x
// 4 points = 32 points per warp). Lane l: slice j = l&3 owns dims [32j,32j+32)
// of all 4 group points, and owns the argmin bookkeeping of group point j.
// ---------------------------------------------------------------------------
__global__ void __launch_bounds__(TPB, 2)
rvq_main_kernel(const float* __restrict__ x,
                const float* __restrict__ cb,
                float* __restrict__ out) {
    __shared__ ulonglong2 sm[2][KCHUNK * 32];   // 2 x 16KB, swizzled
    __shared__ float red[TPB];

    const int tid  = threadIdx.x;
    const int w    = tid >> 5;
    const int lane = tid & 31;
    const int j    = lane & 3;                  // dim slice / owned point
    const unsigned FULL = 0xffffffffu;
    const u64 NEG1 = pack2(-1.f, -1.f);

    // this thread's 4 points: pt(p) = base4 + p ; owned point = blk*128 + tid
    const int base4 = blockIdx.x * TPB + w * 32 + (lane >> 2) * 4;
    const int own   = blockIdx.x * TPB + tid;

    const ulonglong2* x2  = (const ulonglong2*)x;
    const ulonglong2* cb2 = (const ulonglong2*)cb;

    // residual: 4 points x 16 packed f32x2 (32 dims) = 128 regs
    u64 r2[4][16];
#pragma unroll
    for (int p = 0; p < 4; p++) {
#pragma unroll
        for (int ii = 0; ii < 8; ii++) {
            ulonglong2 v = __ldg(&x2[(size_t)(base4 + p) * 32 + j * 8 + ii]);
            r2[p][2 * ii] = v.x;
            r2[p][2 * ii + 1] = v.y;
        }
    }

    float lossl = 0.f;

    for (int s = 0; s < NSTG; s++) {
        const ulonglong2* C2 = cb2 + (size_t)s * KCB * 32;
        const float* hc = g_chalf + s * KCB;

        // ||r||^2 partials -> transpose-reduce so lane j gets its own point's rn
        float rnp[4];
#pragma unroll
        for (int p = 0; p < 4; p++) {
            u64 q = 0ull;
#pragma unroll
            for (int ii = 0; ii < 16; ii++) q = fma2(r2[p][ii], r2[p][ii], q);
            float lo, hi; unpack2(q, lo, hi);
            rnp[p] = lo + hi;
        }
        float rA = ((j & 1) ? rnp[1] : rnp[0]) +
                   __shfl_xor_sync(FULL, (j & 1) ? rnp[0] : rnp[1], 1);
        float rB = ((j & 1) ? rnp[3] : rnp[2]) +
                   __shfl_xor_sync(FULL, (j & 1) ? rnp[2] : rnp[3], 1);
        float rn_own = ((j >> 1) ? rB : rA) +
                       __shfl_xor_sync(FULL, (j >> 1) ? rA : rB, 2);

        float best_h = 3.402823466e38f;
        int   bestk  = 0;

        // prologue: chunk 0 -> buffer 0 (swizzled)
        {
            const ulonglong2* src = C2;
            ulonglong2* dst = sm[0];
#pragma unroll
            for (int jj = 0; jj < 8; jj++) {
                int f = tid + TPB * jj;
                int phys = (f & ~31) | swz(f & 31);
                cp_async16(&dst[phys], &src[f]);
            }
            cp_commit();
        }

        for (int ch = 0; ch < NCHUNK; ch++) {
            const int buf = ch & 1;
            if (ch + 1 < NCHUNK) {
                const ulonglong2* src = C2 + (size_t)(ch + 1) * KCHUNK * 32;
                ulonglong2* dst = sm[buf ^ 1];
#pragma unroll
                for (int jj = 0; jj < 8; jj++) {
                    int f = tid + TPB * jj;
                    int phys = (f & ~31) | swz(f & 31);
                    cp_async16(&dst[phys], &src[f]);
                }
                cp_commit();
                cp_wait1();
            } else {
                cp_wait0();
            }
            __syncthreads();

            const ulonglong2* smb = sm[buf];
            const int kbase = ch * KCHUNK;

#pragma unroll 2
            for (int c = 0; c < KCHUNK; c++) {
                // load this codeword's 32-dim slice (8 LDS.128, bank-clean)
                u64 cw[16];
#pragma unroll
                for (int ii = 0; ii < 8; ii++) {
                    ulonglong2 v = smb[(c << 5) | (j << 3) | ((ii + j) & 7)];
                    cw[2 * ii] = v.x;
                    cw[2 * ii + 1] = v.y;
                }
                u64 a0 = 0ull, a1 = 0ull, a2 = 0ull, a3 = 0ull;
#pragma unroll
                for (int ii = 0; ii < 16; ii++) {
                    a0 = fma2(r2[0][ii], cw[ii], a0);
                    a1 = fma2(r2[1][ii], cw[ii], a1);
                    a2 = fma2(r2[2][ii], cw[ii], a2);
                    a3 = fma2(r2[3][ii], cw[ii], a3);
                }
                float l0, h0, l1, h1, l2, h2, l3, h3;
                unpack2(a0, l0, h0); unpack2(a1, l1, h1);
                unpack2(a2, l2, h2); unpack2(a3, l3, h3);
                float d0 = l0 + h0, d1 = l1 + h1, d2 = l2 + h2, d3 = l3 + h3;

                // transpose-reduce across the 4-lane group: lane j ends with dot[j]
                float A = ((j & 1) ? d1 : d0) +
                          __shfl_xor_sync(FULL, (j & 1) ? d0 : d1, 1);
                float B = ((j & 1) ? d3 : d2) +
                          __shfl_xor_sync(FULL, (j & 1) ? d2 : d3, 1);
                float dot = ((j >> 1) ? B : A) +
                            __shfl_xor_sync(FULL, (j >> 1) ? A : B, 2);

                int k = kbase + c;
                float sc = __ldg(&hc[k]) - dot;     // 0.5*||c||^2 - r.c
                if (sc < best_h) { best_h = sc; bestk = k; }
            }
            __syncthreads();
        }

        // loss: min dist = ||r||^2 + 2*(0.5||c||^2 - r.c)  (bitwise == cn-2dot)
        lossl += rn_own + 2.f * best_h;

        // indices out: [N,S] floats after x_q (N*D) and loss (1)
        out[(size_t)N_PTS * DIM + 1 + (size_t)own * NSTG + s] = (float)bestk;

        // residual update r -= C[bestk_p] for each of the 4 group points
        const int grpbase = lane & ~3;
#pragma unroll
        for (int p = 0; p < 4; p++) {
            int bk = __shfl_sync(FULL, bestk, grpbase + p);
            const ulonglong2* cw = C2 + (size_t)bk * 32 + j * 8;
#pragma unroll
            for (int ii = 0; ii < 8; ii++) {
                ulonglong2 v = __ldg(&cw[ii]);
                r2[p][2 * ii]     = fma2(v.x, NEG1, r2[p][2 * ii]);     // r - c
                r2[p][2 * ii + 1] = fma2(v.y, NEG1, r2[p][2 * ii + 1]);
            }
        }
    }

    // x_q = x - residual_final
    ulonglong2* out2 = (ulonglong2*)out;
#pragma unroll
    for (int p = 0; p < 4; p++) {
#pragma unroll
        for (int ii = 0; ii < 8; ii++) {
            size_t idx = (size_t)(base4 + p) * 32 + j * 8 + ii;
            ulonglong2 xv = __ldg(&x2[idx]);
            ulonglong2 o;
            o.x = fma2(r2[p][2 * ii],     NEG1, xv.x);
            o.y = fma2(r2[p][2 * ii + 1], NEG1, xv.y);
            out2[idx] = o;
        }
    }

    // deterministic block reduction of per-point losses
    red[tid] = lossl;
    __syncthreads();
#pragma unroll
    for (int off = TPB / 2; off > 0; off >>= 1) {
        if (tid < off) red[tid] += red[tid + off];
        __syncthreads();
    }
    if (tid == 0) g_partial[blockIdx.x] = red[0];
}

// ---------------------------------------------------------------------------
// Kernel 2: final loss = 1.25 * sum(dist_min) / (S*N*D)
// ---------------------------------------------------------------------------
__global__ void rvq_loss_kernel(float* __restrict__ out) {
    __shared__ float red[NBLK];
    int t = threadIdx.x;
    red[t] = g_partial[t];
    __syncthreads();
#pragma unroll
    for (int off = NBLK / 2; off > 0; off >>= 1) {
        if (t < off) red[t] += red[t + off];
        __syncthreads();
    }
    if (t == 0) {
        float scale = 1.25f / ((float)NSTG * (float)N_PTS * (float)DIM);
        out[(size_t)N_PTS * DIM] = red[0] * scale;
    }
}

// ---------------------------------------------------------------------------
extern "C" void kernel_launch(void* const* d_in, const int* in_sizes, int n_in,
                              void* d_out, int out_size) {
    const float* x  = (const float*)d_in[0];   // [N, D] float32
    const float* cb = (const float*)d_in[1];   // [S, K, D] float32
    float* out = (float*)d_out;                // [N*D | 1 | N*S] float32

    rvq_cnorm_kernel<<<(NSTG * KCB + 127) / 128, 128>>>(cb);
    rvq_main_kernel<<<NBLK, TPB>>>(x, cb, out);
    rvq_loss_kernel<<<1, NBLK>>>(out);
}

// round 3
// speedup vs baseline: 4.7936x; 1.7416x over previous
#include <cuda_runtime.h>
#include <cstdint>

// Fixed shapes
#define N_PTS   65536
#define DIM     128
#define NSTG    4
#define KCB     2048
#define TPB     128
#define NBLK    (N_PTS / TPB)     // 512
#define TN      32                // codewords per tile
#define NTILE   (KCB / TN)        // 64
#define RSTRIDE 132               // padded floats per row (conflict-free frags)
#define CAP     16                // candidate cap per point
#define MARGIN  0.25f             // in half-distance units (hc - dot)

typedef uint32_t u32;

// Scratch (no cudaMalloc allowed)
__device__ float g_chalf[NSTG * KCB];    // 0.5 * ||C_k||^2
__device__ float g_partial[NBLK];

// ---------------- helpers ----------------------------------------------------
__device__ __forceinline__ void cp_async16(void* smem_ptr, const void* gmem_ptr) {
    unsigned s = (unsigned)__cvta_generic_to_shared(smem_ptr);
    asm volatile("cp.async.cg.shared.global [%0], [%1], 16;" :: "r"(s), "l"(gmem_ptr));
}
__device__ __forceinline__ void cp_commit() { asm volatile("cp.async.commit_group;"); }
__device__ __forceinline__ void cp_wait1()  { asm volatile("cp.async.wait_group 1;"); }
__device__ __forceinline__ void cp_wait0()  { asm volatile("cp.async.wait_group 0;"); }

// mma.m16n8k8 tf32: A row-major frag (4 regs), B col-major frag (2 regs), C fp32 (4)
__device__ __forceinline__ void mma_tf32(float& c0, float& c1, float& c2, float& c3,
                                         u32 a0, u32 a1, u32 a2, u32 a3,
                                         u32 b0, u32 b1) {
    asm volatile(
        "mma.sync.aligned.m16n8k8.row.col.f32.tf32.tf32.f32 "
        "{%0,%1,%2,%3}, {%4,%5,%6,%7}, {%8,%9}, {%0,%1,%2,%3};"
        : "+f"(c0), "+f"(c1), "+f"(c2), "+f"(c3)
        : "r"(a0), "r"(a1), "r"(a2), "r"(a3), "r"(b0), "r"(b1));
}

// bf16 bits of f rounded toward -inf (stored value <= f)
__device__ __forceinline__ u32 bf16_rd(float f) {
    u32 u = __float_as_uint(f);
    u32 b = u >> 16;
    if ((u & 0xFFFFu) && (u >> 31)) b++;   // negative: truncation rounded up; push down
    return b & 0xFFFFu;
}

// ---------------------------------------------------------------------------
// Kernel 0: half squared norms
// ---------------------------------------------------------------------------
__global__ void rvq_cnorm_kernel(const float* __restrict__ cb) {
    int c = blockIdx.x * blockDim.x + threadIdx.x;
    if (c >= NSTG * KCB) return;
    const float4* row = (const float4*)(cb + (size_t)c * DIM);
    float s = 0.f;
#pragma unroll
    for (int i = 0; i < 32; i++) {
        float4 v = row[i];
        s += v.x * v.x + v.y * v.y + v.z * v.z + v.w * v.w;
    }
    g_chalf[c] = 0.5f * s;
}

// ---------------------------------------------------------------------------
// Kernel 1: fused RVQ. 128 points per CTA. Per stage:
//   tf32 MMA sweep over all 2048 codewords -> coarse min + candidate lists
//   exact fp32 rescore of candidates -> argmin, loss, residual update
// ---------------------------------------------------------------------------
__global__ void __launch_bounds__(TPB, 2)
rvq_main_kernel(const float* __restrict__ x,
                const float* __restrict__ cb,
                float* __restrict__ out) {
    extern __shared__ char smraw[];
    float* rsm   = (float*)smraw;                         // 128*132 fp32 residual
    float* cbt   = rsm + TPB * RSTRIDE;                   // 2 * 32*132 codeword tiles
    float* hct   = cbt + 2 * TN * RSTRIDE;                // 2 * 32 half-norms
    u32*   ccnt  = (u32*)(hct + 2 * TN);                  // 128 counters
    u32*   clist = ccnt + TPB;                            // 128 * CAP entries
    float* cmin  = (float*)(clist + TPB * CAP);           // 128 coarse mins
    float* red   = cmin + TPB;                            // 128 reduction

    const int tid  = threadIdx.x;
    const int w    = tid >> 5;
    const int lane = tid & 31;
    const int g    = lane >> 2;      // group id (0..7)
    const int t    = lane & 3;       // thread in group
    const int w32  = w * 32;         // warp's point base within CTA
    const unsigned FULL = 0xffffffffu;

    const u32* rsmu = (const u32*)rsm;

    // ---- load x block into rsm (residual master) ----
    {
        const float4* x4 = (const float4*)x;
        float4* rsm4 = (float4*)rsm;
#pragma unroll
        for (int jj = 0; jj < 32; jj++) {
            int row = jj * 4 + (tid >> 5);
            int c4  = tid & 31;
            rsm4[row * (RSTRIDE / 4) + c4] =
                __ldg(&x4[((size_t)blockIdx.x * TPB + row) * 32 + c4]);
        }
    }

    float lossl = 0.f;
    int   idx_reg[NSTG];

    for (int s = 0; s < NSTG; s++) {
        const float* Cs  = cb + (size_t)s * KCB * DIM;
        const float* hcs = g_chalf + s * KCB;

        // reset candidate counters (rsm also now stable for this stage)
        ccnt[tid] = 0;
        __syncthreads();

        // per-lane running row mins for the 4 row-slots this lane touches
        float rowmin[4] = {3.402823466e38f, 3.402823466e38f,
                           3.402823466e38f, 3.402823466e38f};

        // prologue: tile 0 -> buffer 0
        {
            float* dst = cbt;
#pragma unroll
            for (int jj = 0; jj < 8; jj++) {
                int f = tid + TPB * jj;            // 0..1023 float4 slots
                int r = f >> 5, c4 = f & 31;
                cp_async16(dst + r * RSTRIDE + c4 * 4, Cs + (size_t)r * DIM + c4 * 4);
            }
            if (tid < 8) cp_async16(hct + tid * 4, hcs + tid * 4);
            cp_commit();
        }

        for (int ch = 0; ch < NTILE; ch++) {
            const int buf = ch & 1;
            if (ch + 1 < NTILE) {
                float* dst = cbt + (buf ^ 1) * TN * RSTRIDE;
                const float* src = Cs + (size_t)(ch + 1) * TN * DIM;
#pragma unroll
                for (int jj = 0; jj < 8; jj++) {
                    int f = tid + TPB * jj;
                    int r = f >> 5, c4 = f & 31;
                    cp_async16(dst + r * RSTRIDE + c4 * 4, src + (size_t)r * DIM + c4 * 4);
                }
                if (tid < 8)
                    cp_async16(hct + (buf ^ 1) * TN + tid * 4,
                               hcs + (ch + 1) * TN + tid * 4);
                cp_commit();
                cp_wait1();
            } else {
                cp_wait0();
            }
            __syncthreads();

            const u32*   cbu = (const u32*)(cbt + buf * TN * RSTRIDE);
            const float* hcb = hct + buf * TN;

            // accumulators: [mtile][ntile][4]
            float acc[2][4][4];
#pragma unroll
            for (int m = 0; m < 2; m++)
#pragma unroll
                for (int n = 0; n < 4; n++)
#pragma unroll
                    for (int i = 0; i < 4; i++) acc[m][n][i] = 0.f;

#pragma unroll
            for (int kb = 0; kb < DIM; kb += 8) {
                u32 a[2][4];
#pragma unroll
                for (int m = 0; m < 2; m++) {
                    int r0 = (w32 + m * 16 + g) * RSTRIDE + kb + t;
                    int r1 = (w32 + m * 16 + g + 8) * RSTRIDE + kb + t;
                    a[m][0] = rsmu[r0];
                    a[m][1] = rsmu[r1];
                    a[m][2] = rsmu[r0 + 4];
                    a[m][3] = rsmu[r1 + 4];
                }
#pragma unroll
                for (int n = 0; n < 4; n++) {
                    int bi = (n * 8 + g) * RSTRIDE + kb + t;
                    u32 b0 = cbu[bi];
                    u32 b1 = cbu[bi + 4];
                    mma_tf32(acc[0][n][0], acc[0][n][1], acc[0][n][2], acc[0][n][3],
                             a[0][0], a[0][1], a[0][2], a[0][3], b0, b1);
                    mma_tf32(acc[1][n][0], acc[1][n][1], acc[1][n][2], acc[1][n][3],
                             a[1][0], a[1][1], a[1][2], a[1][3], b0, b1);
                }
            }

            // epilogue: dot -> coarse half-dist; tile mins; candidate appends
            const int kbase = ch * TN;
            float tmin[4] = {3.402823466e38f, 3.402823466e38f,
                             3.402823466e38f, 3.402823466e38f};
#pragma unroll
            for (int m = 0; m < 2; m++) {
#pragma unroll
                for (int n = 0; n < 4; n++) {
                    float h0 = hcb[n * 8 + 2 * t];
                    float h1 = hcb[n * 8 + 2 * t + 1];
                    float d0 = h0 - acc[m][n][0];
                    float d1 = h1 - acc[m][n][1];
                    float d2 = h0 - acc[m][n][2];
                    float d3 = h1 - acc[m][n][3];
                    acc[m][n][0] = d0; acc[m][n][1] = d1;
                    acc[m][n][2] = d2; acc[m][n][3] = d3;
                    float mA = fminf(d0, d1);   // row g slot
                    float mB = fminf(d2, d3);   // row g+8 slot
                    tmin[m * 2]     = fminf(tmin[m * 2], mA);
                    tmin[m * 2 + 1] = fminf(tmin[m * 2 + 1], mB);
                }
            }
#pragma unroll
            for (int sl = 0; sl < 4; sl++) {
                float v = fminf(rowmin[sl], tmin[sl]);
                v = fminf(v, __shfl_xor_sync(FULL, v, 1));
                v = fminf(v, __shfl_xor_sync(FULL, v, 2));
                rowmin[sl] = v;
            }
            // appends (rare)
#pragma unroll
            for (int m = 0; m < 2; m++) {
#pragma unroll
                for (int n = 0; n < 4; n++) {
#pragma unroll
                    for (int i = 0; i < 4; i++) {
                        int sl = m * 2 + (i >> 1);
                        float d = acc[m][n][i];
                        if (d < rowmin[sl] + MARGIN) {
                            int k  = kbase + n * 8 + 2 * t + (i & 1);
                            int pt = w32 + m * 16 + g + ((i >> 1) ? 8 : 0);
                            u32 pos = atomicAdd(&ccnt[pt], 1u);
                            if (pos < CAP)
                                clist[pt * CAP + pos] = (bf16_rd(d) << 16) | (u32)k;
                        }
                    }
                }
            }
            __syncthreads();
        }

        // publish coarse mins (all quad lanes agree; lane t==0 writes)
        if (t == 0) {
            cmin[w32 + g]      = rowmin[0];
            cmin[w32 + g + 8]  = rowmin[1];
            cmin[w32 + g + 16] = rowmin[2];
            cmin[w32 + g + 24] = rowmin[3];
        }
        __syncthreads();

        // ---- exact rescore: thread tid owns point tid ----
        const float4* rrow = (const float4*)(rsm + tid * RSTRIDE);
        float cm  = cmin[tid];
        u32   cnt = ccnt[tid];

        float bestd = 3.402823466e38f;
        int   bestk = 0;

        if (cnt <= CAP) {
            for (u32 e = 0; e < cnt; e++) {
                u32 ent = clist[tid * CAP + e];
                float dcoarse = __uint_as_float((ent >> 16) << 16);
                if (dcoarse > cm + MARGIN) continue;
                int k = (int)(ent & 0xFFFFu);
                const float4* crow = (const float4*)(Cs + (size_t)k * DIM);
                float dot = 0.f;
#pragma unroll
                for (int i = 0; i < 32; i++) {
                    float4 c = __ldg(&crow[i]);
                    float4 rv = rrow[i];
                    dot = fmaf(rv.x, c.x, dot);
                    dot = fmaf(rv.y, c.y, dot);
                    dot = fmaf(rv.z, c.z, dot);
                    dot = fmaf(rv.w, c.w, dot);
                }
                float dh = __ldg(&hcs[k]) - dot;
                if (dh < bestd || (dh == bestd && k < bestk)) { bestd = dh; bestk = k; }
            }
        } else {
            // overflow fallback: exact scan of all codewords (rare)
            for (int k = 0; k < KCB; k++) {
                const float4* crow = (const float4*)(Cs + (size_t)k * DIM);
                float dot = 0.f;
#pragma unroll
                for (int i = 0; i < 32; i++) {
                    float4 c = __ldg(&crow[i]);
                    float4 rv = rrow[i];
                    dot = fmaf(rv.x, c.x, dot);
                    dot = fmaf(rv.y, c.y, dot);
                    dot = fmaf(rv.z, c.z, dot);
                    dot = fmaf(rv.w, c.w, dot);
                }
                float dh = __ldg(&hcs[k]) - dot;
                if (dh < bestd) { bestd = dh; bestk = k; }
            }
        }
        idx_reg[s] = bestk;

        // ||r||^2 exact + loss:  min dist = rn + 2*(hc - dot)
        {
            float rn = 0.f;
#pragma unroll
            for (int i = 0; i < 32; i++) {
                float4 rv = rrow[i];
                rn = fmaf(rv.x, rv.x, rn);
                rn = fmaf(rv.y, rv.y, rn);
                rn = fmaf(rv.z, rv.z, rn);
                rn = fmaf(rv.w, rv.w, rn);
            }
            lossl += rn + 2.f * bestd;
        }

        // residual update: r -= C[bestk]
        {
            float4* wrow = (float4*)(rsm + tid * RSTRIDE);
            const float4* crow = (const float4*)(Cs + (size_t)bestk * DIM);
#pragma unroll
            for (int i = 0; i < 32; i++) {
                float4 c = __ldg(&crow[i]);
                float4 rv = wrow[i];
                rv.x -= c.x; rv.y -= c.y; rv.z -= c.z; rv.w -= c.w;
                wrow[i] = rv;
            }
        }
        __syncthreads();
    }

    // ---- x_q = x - residual_final (coalesced, cooperative) ----
    {
        const float4* x4 = (const float4*)x;
        float4* out4 = (float4*)out;
        const float4* rsm4 = (const float4*)rsm;
#pragma unroll
        for (int jj = 0; jj < 32; jj++) {
            int row = jj * 4 + (tid >> 5);
            int c4  = tid & 31;
            size_t gi = ((size_t)blockIdx.x * TPB + row) * 32 + c4;
            float4 xv = __ldg(&x4[gi]);
            float4 rv = rsm4[row * (RSTRIDE / 4) + c4];
            float4 o;
            o.x = xv.x - rv.x; o.y = xv.y - rv.y;
            o.z = xv.z - rv.z; o.w = xv.w - rv.w;
            out4[gi] = o;
        }
    }

    // indices: [N, S] floats after x_q and loss scalar
    {
        int n = blockIdx.x * TPB + tid;
#pragma unroll
        for (int s = 0; s < NSTG; s++)
            out[(size_t)N_PTS * DIM + 1 + (size_t)n * NSTG + s] = (float)idx_reg[s];
    }

    // deterministic loss partial
    red[tid] = lossl;
    __syncthreads();
#pragma unroll
    for (int off = TPB / 2; off > 0; off >>= 1) {
        if (tid < off) red[tid] += red[tid + off];
        __syncthreads();
    }
    if (tid == 0) g_partial[blockIdx.x] = red[0];
}

// ---------------------------------------------------------------------------
// Kernel 2: final loss = 1.25 * sum(min dist) / (S*N*D)
// ---------------------------------------------------------------------------
__global__ void rvq_loss_kernel(float* __restrict__ out) {
    __shared__ float red[NBLK];
    int t = threadIdx.x;
    red[t] = g_partial[t];
    __syncthreads();
#pragma unroll
    for (int off = NBLK / 2; off > 0; off >>= 1) {
        if (t < off) red[t] += red[t + off];
        __syncthreads();
    }
    if (t == 0) {
        float scale = 1.25f / ((float)NSTG * (float)N_PTS * (float)DIM);
        out[(size_t)N_PTS * DIM] = red[0] * scale;
    }
}

// ---------------------------------------------------------------------------
extern "C" void kernel_launch(void* const* d_in, const int* in_sizes, int n_in,
                              void* d_out, int out_size) {
    const float* x  = (const float*)d_in[0];   // [N, D]
    const float* cb = (const float*)d_in[1];   // [S, K, D]
    float* out = (float*)d_out;                // [N*D | 1 | N*S]

    const int smem_bytes =
        TPB * RSTRIDE * 4 +            // rsm
        2 * TN * RSTRIDE * 4 +         // cbt
        2 * TN * 4 +                   // hct
        TPB * 4 +                      // ccnt
        TPB * CAP * 4 +                // clist
        TPB * 4 +                      // cmin
        TPB * 4;                       // red

    cudaFuncSetAttribute(rvq_main_kernel,
                         cudaFuncAttributeMaxDynamicSharedMemorySize, smem_bytes);

    rvq_cnorm_kernel<<<(NSTG * KCB + 127) / 128, 128>>>(cb);
    rvq_main_kernel<<<NBLK, TPB, smem_bytes>>>(x, cb, out);
    rvq_loss_kernel<<<1, NBLK>>>(out);
}

// round 4
// speedup vs baseline: 11.9128x; 2.4852x over previous
#include <cuda_runtime.h>
#include <cstdint>

// Fixed shapes
#define N_PTS   65536
#define DIM     128
#define NSTG    4
#define KCB     2048
#define TPB     128
#define NBLK    (N_PTS / TPB)     // 512
#define TN      32                // codewords per tile
#define NTILE   (KCB / TN)        // 64
#define RSTRIDE 132               // fp32 residual row stride
#define BSTRIDE 68                // u32 (bf16x2) codeword row stride in smem
#define CAP     24                // candidate cap per point
#define MARGIN  0.5f              // half-distance units

typedef uint32_t u32;

// Scratch (no cudaMalloc allowed)
__device__ float g_chalf[NSTG * KCB];          // 0.5 * ||C_k||^2 (exact fp32)
__device__ u32   g_cbh[NSTG * KCB * 64];       // bf16x2-packed codebook (k-pairs)
__device__ float g_partial[NBLK];

// ---------------- helpers ----------------------------------------------------
__device__ __forceinline__ void cp_async16(void* smem_ptr, const void* gmem_ptr) {
    unsigned s = (unsigned)__cvta_generic_to_shared(smem_ptr);
    asm volatile("cp.async.cg.shared.global [%0], [%1], 16;" :: "r"(s), "l"(gmem_ptr));
}
__device__ __forceinline__ void cp_commit() { asm volatile("cp.async.commit_group;"); }
__device__ __forceinline__ void cp_wait1()  { asm volatile("cp.async.wait_group 1;"); }
__device__ __forceinline__ void cp_wait0()  { asm volatile("cp.async.wait_group 0;"); }

// pack {lo = bf16(a), hi = bf16(b)} ; first cvt source goes to the upper half
__device__ __forceinline__ u32 pack_bf(float lo, float hi) {
    u32 d;
    asm("cvt.rn.bf16x2.f32 %0, %1, %2;" : "=r"(d) : "f"(hi), "f"(lo));
    return d;
}

// mma m16n8k16 bf16: A row-major (4 regs), B col-major (2 regs), C fp32 (4)
__device__ __forceinline__ void mma_bf16(float& c0, float& c1, float& c2, float& c3,
                                         u32 a0, u32 a1, u32 a2, u32 a3,
                                         u32 b0, u32 b1) {
    asm volatile(
        "mma.sync.aligned.m16n8k16.row.col.f32.bf16.bf16.f32 "
        "{%0,%1,%2,%3}, {%4,%5,%6,%7}, {%8,%9}, {%0,%1,%2,%3};"
        : "+f"(c0), "+f"(c1), "+f"(c2), "+f"(c3)
        : "r"(a0), "r"(a1), "r"(a2), "r"(a3), "r"(b0), "r"(b1));
}

// bf16 bits of f rounded toward -inf (stored value <= f)
__device__ __forceinline__ u32 bf16_rd(float f) {
    u32 u = __float_as_uint(f);
    u32 b = u >> 16;
    if ((u & 0xFFFFu) && (u >> 31)) b++;
    return b & 0xFFFFu;
}

// ---------------------------------------------------------------------------
// Kernel 0: per-codeword half norms (exact fp32) + bf16x2-packed codebook copy
// ---------------------------------------------------------------------------
__global__ void rvq_prep_kernel(const float* __restrict__ cb) {
    int c = blockIdx.x * blockDim.x + threadIdx.x;
    if (c >= NSTG * KCB) return;
    const float4* row = (const float4*)(cb + (size_t)c * DIM);
    u32* dst = g_cbh + (size_t)c * 64;
    float s = 0.f;
#pragma unroll
    for (int i = 0; i < 32; i++) {
        float4 v = row[i];
        s += v.x * v.x + v.y * v.y + v.z * v.z + v.w * v.w;
        dst[2 * i]     = pack_bf(v.x, v.y);
        dst[2 * i + 1] = pack_bf(v.z, v.w);
    }
    g_chalf[c] = 0.5f * s;
}

// ---------------------------------------------------------------------------
// Kernel 1: fused RVQ. 128 points per CTA. Per stage:
//   bf16 MMA sweep (A in regs) -> coarse mins + margin candidate lists
//   exact fp32 rescore -> argmin, loss, residual update
// ---------------------------------------------------------------------------
__global__ void __launch_bounds__(TPB, 2)
rvq_main_kernel(const float* __restrict__ x,
                const float* __restrict__ cb,
                float* __restrict__ out) {
    extern __shared__ char smraw[];
    float* rsm   = (float*)smraw;                    // 128*132 fp32 residual master
    u32*   cbt   = (u32*)(rsm + TPB * RSTRIDE);      // 2 * 32*68 bf16x2 tiles
    float* hct   = (float*)(cbt + 2 * TN * BSTRIDE); // 2 * 32 half-norms
    u32*   ccnt  = (u32*)(hct + 2 * TN);             // 128 counters
    u32*   clist = ccnt + TPB;                       // 128 * CAP entries
    float* cmin  = (float*)(clist + TPB * CAP);      // 128 coarse mins
    float* red   = cmin + TPB;                       // 128 reduction

    const int tid  = threadIdx.x;
    const int w    = tid >> 5;
    const int lane = tid & 31;
    const int g    = lane >> 2;
    const int t    = lane & 3;
    const int w32  = w * 32;
    const unsigned FULL = 0xffffffffu;

    // ---- load x block into rsm ----
    {
        const float4* x4 = (const float4*)x;
        float4* rsm4 = (float4*)rsm;
#pragma unroll
        for (int jj = 0; jj < 32; jj++) {
            int row = jj * 4 + (tid >> 5);
            int c4  = tid & 31;
            rsm4[row * (RSTRIDE / 4) + c4] =
                __ldg(&x4[((size_t)blockIdx.x * TPB + row) * 32 + c4]);
        }
    }

    float lossl = 0.f;
    int   idx_reg[NSTG];

    for (int s = 0; s < NSTG; s++) {
        const float* Cs  = cb + (size_t)s * KCB * DIM;
        const float* hcs = g_chalf + s * KCB;
        const u32*   Ch  = g_cbh + (size_t)s * KCB * 64;

        ccnt[tid] = 0;
        __syncthreads();

        // ---- convert this warp's residual rows into bf16x2 A-fragments ----
        // areg[m][r01][u] : row = w32 + m*16 + g + r01*8, pair j = t + 4u
        u32 areg[2][2][16];
#pragma unroll
        for (int m = 0; m < 2; m++) {
#pragma unroll
            for (int r01 = 0; r01 < 2; r01++) {
                const float* rp = rsm + (w32 + m * 16 + g + r01 * 8) * RSTRIDE;
#pragma unroll
                for (int u = 0; u < 16; u++) {
                    int j = t + 4 * u;
                    float2 v = *(const float2*)(rp + 2 * j);
                    areg[m][r01][u] = pack_bf(v.x, v.y);
                }
            }
        }

        float rowmin[4] = {3.402823466e38f, 3.402823466e38f,
                           3.402823466e38f, 3.402823466e38f};

        // prologue: tile 0 -> buffer 0
        {
#pragma unroll
            for (int jj = 0; jj < 4; jj++) {
                int f = tid + TPB * jj;            // 512 16B-chunks
                int cw = f >> 4, chx = f & 15;
                cp_async16(cbt + cw * BSTRIDE + chx * 4, Ch + (size_t)cw * 64 + chx * 4);
            }
            if (tid < 8) cp_async16(hct + tid * 4, hcs + tid * 4);
            cp_commit();
        }

        for (int ch = 0; ch < NTILE; ch++) {
            const int buf = ch & 1;
            if (ch + 1 < NTILE) {
                u32* dst = cbt + (buf ^ 1) * TN * BSTRIDE;
                const u32* src = Ch + (size_t)(ch + 1) * TN * 64;
#pragma unroll
                for (int jj = 0; jj < 4; jj++) {
                    int f = tid + TPB * jj;
                    int cw = f >> 4, chx = f & 15;
                    cp_async16(dst + cw * BSTRIDE + chx * 4, src + (size_t)cw * 64 + chx * 4);
                }
                if (tid < 8)
                    cp_async16(hct + (buf ^ 1) * TN + tid * 4,
                               hcs + (ch + 1) * TN + tid * 4);
                cp_commit();
                cp_wait1();
            } else {
                cp_wait0();
            }
            __syncthreads();

            const u32*   cbu = cbt + buf * TN * BSTRIDE;
            const float* hcb = hct + buf * TN;

            float acc[2][4][4];
#pragma unroll
            for (int m = 0; m < 2; m++)
#pragma unroll
                for (int n = 0; n < 4; n++)
#pragma unroll
                    for (int i = 0; i < 4; i++) acc[m][n][i] = 0.f;

#pragma unroll
            for (int q = 0; q < 8; q++) {           // k-steps of 16
#pragma unroll
                for (int n = 0; n < 4; n++) {
                    int bi = (n * 8 + g) * BSTRIDE + 8 * q + t;
                    u32 b0 = cbu[bi];
                    u32 b1 = cbu[bi + 4];
                    mma_bf16(acc[0][n][0], acc[0][n][1], acc[0][n][2], acc[0][n][3],
                             areg[0][0][2 * q], areg[0][1][2 * q],
                             areg[0][0][2 * q + 1], areg[0][1][2 * q + 1], b0, b1);
                    mma_bf16(acc[1][n][0], acc[1][n][1], acc[1][n][2], acc[1][n][3],
                             areg[1][0][2 * q], areg[1][1][2 * q],
                             areg[1][0][2 * q + 1], areg[1][1][2 * q + 1], b0, b1);
                }
            }

            // epilogue: half-dists, tile mins, margin appends
            const int kbase = ch * TN;
            float tmin[4] = {3.402823466e38f, 3.402823466e38f,
                             3.402823466e38f, 3.402823466e38f};
#pragma unroll
            for (int m = 0; m < 2; m++) {
#pragma unroll
                for (int n = 0; n < 4; n++) {
                    float h0 = hcb[n * 8 + 2 * t];
                    float h1 = hcb[n * 8 + 2 * t + 1];
                    float d0 = h0 - acc[m][n][0];
                    float d1 = h1 - acc[m][n][1];
                    float d2 = h0 - acc[m][n][2];
                    float d3 = h1 - acc[m][n][3];
                    acc[m][n][0] = d0; acc[m][n][1] = d1;
                    acc[m][n][2] = d2; acc[m][n][3] = d3;
                    tmin[m * 2]     = fminf(tmin[m * 2],     fminf(d0, d1));
                    tmin[m * 2 + 1] = fminf(tmin[m * 2 + 1], fminf(d2, d3));
                }
            }
#pragma unroll
            for (int sl = 0; sl < 4; sl++) {
                float v = fminf(rowmin[sl], tmin[sl]);
                v = fminf(v, __shfl_xor_sync(FULL, v, 1));
                v = fminf(v, __shfl_xor_sync(FULL, v, 2));
                rowmin[sl] = v;
            }
#pragma unroll
            for (int m = 0; m < 2; m++) {
#pragma unroll
                for (int n = 0; n < 4; n++) {
#pragma unroll
                    for (int i = 0; i < 4; i++) {
                        int sl = m * 2 + (i >> 1);
                        float d = acc[m][n][i];
                        if (d < rowmin[sl] + MARGIN) {
                            int k  = kbase + n * 8 + 2 * t + (i & 1);
                            int pt = w32 + m * 16 + g + ((i >> 1) ? 8 : 0);
                            u32 pos = atomicAdd(&ccnt[pt], 1u);
                            if (pos < CAP)
                                clist[pt * CAP + pos] = (bf16_rd(d) << 16) | (u32)k;
                        }
                    }
                }
            }
            __syncthreads();
        }

        if (t == 0) {
            cmin[w32 + g]      = rowmin[0];
            cmin[w32 + g + 8]  = rowmin[1];
            cmin[w32 + g + 16] = rowmin[2];
            cmin[w32 + g + 24] = rowmin[3];
        }
        __syncthreads();

        // ---- exact fp32 rescore: thread tid owns point tid ----
        const float4* rrow = (const float4*)(rsm + tid * RSTRIDE);
        float cm  = cmin[tid];
        u32   cnt = ccnt[tid];

        float bestd = 3.402823466e38f;
        int   bestk = 0;

        if (cnt <= CAP) {
            for (u32 e = 0; e < cnt; e++) {
                u32 ent = clist[tid * CAP + e];
                float dcoarse = __uint_as_float((ent >> 16) << 16);
                if (dcoarse > cm + MARGIN) continue;
                int k = (int)(ent & 0xFFFFu);
                const float4* crow = (const float4*)(Cs + (size_t)k * DIM);
                float dot = 0.f;
#pragma unroll
                for (int i = 0; i < 32; i++) {
                    float4 c = __ldg(&crow[i]);
                    float4 rv = rrow[i];
                    dot = fmaf(rv.x, c.x, dot);
                    dot = fmaf(rv.y, c.y, dot);
                    dot = fmaf(rv.z, c.z, dot);
                    dot = fmaf(rv.w, c.w, dot);
                }
                float dh = __ldg(&hcs[k]) - dot;
                if (dh < bestd || (dh == bestd && k < bestk)) { bestd = dh; bestk = k; }
            }
        } else {
            for (int k = 0; k < KCB; k++) {          // rare overflow fallback
                const float4* crow = (const float4*)(Cs + (size_t)k * DIM);
                float dot = 0.f;
#pragma unroll
                for (int i = 0; i < 32; i++) {
                    float4 c = __ldg(&crow[i]);
                    float4 rv = rrow[i];
                    dot = fmaf(rv.x, c.x, dot);
                    dot = fmaf(rv.y, c.y, dot);
                    dot = fmaf(rv.z, c.z, dot);
                    dot = fmaf(rv.w, c.w, dot);
                }
                float dh = __ldg(&hcs[k]) - dot;
                if (dh < bestd) { bestd = dh; bestk = k; }
            }
        }
        idx_reg[s] = bestk;

        // loss: min dist = ||r||^2 + 2*(hc - dot)
        {
            float rn = 0.f;
#pragma unroll
            for (int i = 0; i < 32; i++) {
                float4 rv = rrow[i];
                rn = fmaf(rv.x, rv.x, rn);
                rn = fmaf(rv.y, rv.y, rn);
                rn = fmaf(rv.z, rv.z, rn);
                rn = fmaf(rv.w, rv.w, rn);
            }
            lossl += rn + 2.f * bestd;
        }

        // residual update: r -= C[bestk]
        {
            float4* wrow = (float4*)(rsm + tid * RSTRIDE);
            const float4* crow = (const float4*)(Cs + (size_t)bestk * DIM);
#pragma unroll
            for (int i = 0; i < 32; i++) {
                float4 c = __ldg(&crow[i]);
                float4 rv = wrow[i];
                rv.x -= c.x; rv.y -= c.y; rv.z -= c.z; rv.w -= c.w;
                wrow[i] = rv;
            }
        }
        __syncthreads();
    }

    // ---- x_q = x - residual_final ----
    {
        const float4* x4 = (const float4*)x;
        float4* out4 = (float4*)out;
        const float4* rsm4 = (const float4*)rsm;
#pragma unroll
        for (int jj = 0; jj < 32; jj++) {
            int row = jj * 4 + (tid >> 5);
            int c4  = tid & 31;
            size_t gi = ((size_t)blockIdx.x * TPB + row) * 32 + c4;
            float4 xv = __ldg(&x4[gi]);
            float4 rv = rsm4[row * (RSTRIDE / 4) + c4];
            float4 o;
            o.x = xv.x - rv.x; o.y = xv.y - rv.y;
            o.z = xv.z - rv.z; o.w = xv.w - rv.w;
            out4[gi] = o;
        }
    }

    // indices: [N, S] floats after x_q and loss scalar
    {
        int n = blockIdx.x * TPB + tid;
#pragma unroll
        for (int s = 0; s < NSTG; s++)
            out[(size_t)N_PTS * DIM + 1 + (size_t)n * NSTG + s] = (float)idx_reg[s];
    }

    red[tid] = lossl;
    __syncthreads();
#pragma unroll
    for (int off = TPB / 2; off > 0; off >>= 1) {
        if (tid < off) red[tid] += red[tid + off];
        __syncthreads();
    }
    if (tid == 0) g_partial[blockIdx.x] = red[0];
}

// ---------------------------------------------------------------------------
// Kernel 2: final loss = 1.25 * sum(min dist) / (S*N*D)
// ---------------------------------------------------------------------------
__global__ void rvq_loss_kernel(float* __restrict__ out) {
    __shared__ float red[NBLK];
    int t = threadIdx.x;
    red[t] = g_partial[t];
    __syncthreads();
#pragma unroll
    for (int off = NBLK / 2; off > 0; off >>= 1) {
        if (t < off) red[t] += red[t + off];
        __syncthreads();
    }
    if (t == 0) {
        float scale = 1.25f / ((float)NSTG * (float)N_PTS * (float)DIM);
        out[(size_t)N_PTS * DIM] = red[0] * scale;
    }
}

// ---------------------------------------------------------------------------
extern "C" void kernel_launch(void* const* d_in, const int* in_sizes, int n_in,
                              void* d_out, int out_size) {
    const float* x  = (const float*)d_in[0];   // [N, D]
    const float* cb = (const float*)d_in[1];   // [S, K, D]
    float* out = (float*)d_out;                // [N*D | 1 | N*S]

    const int smem_bytes =
        TPB * RSTRIDE * 4 +            // rsm
        2 * TN * BSTRIDE * 4 +         // cbt (bf16x2)
        2 * TN * 4 +                   // hct
        TPB * 4 +                      // ccnt
        TPB * CAP * 4 +                // clist
        TPB * 4 +                      // cmin
        TPB * 4;                       // red

    cudaFuncSetAttribute(rvq_main_kernel,
                         cudaFuncAttributeMaxDynamicSharedMemorySize, smem_bytes);

    rvq_prep_kernel<<<(NSTG * KCB + 127) / 128, 128>>>(cb);
    rvq_main_kernel<<<NBLK, TPB, smem_bytes>>>(x, cb, out);
    rvq_loss_kernel<<<1, NBLK>>>(out);
}